// round 1
// baseline (speedup 1.0000x reference)
#include <cuda_runtime.h>
#include <cuda_bf16.h>

#define GDIM 128
#define NRAYS 2048
#define NSAMP 128
#define VD 28

// SH constants
#define Y00f 0.28209479177387814f
#define H3f  0.4886025119029199f
#define H15f 1.0925484305920792f
#define Q5f  0.31539156525252005f
#define Q15f 0.5462742152960396f

__global__ __launch_bounds__(NSAMP, 8) void plenoxel_kernel(
    const float* __restrict__ grid,   // (G,G,G,28)
    const float* __restrict__ pos,    // (R,S,3)
    const float* __restrict__ dist,   // (R,S)
    const float* __restrict__ ang,    // (R,2)
    float* __restrict__ out)          // (R,3)
{
    const int r = blockIdx.x;
    const int s = threadIdx.x;
    const int lane = s & 31;
    const int wid = s >> 5;

    __shared__ float Ysh[9];
    __shared__ float warp_att[4];
    __shared__ float warp_rgb[4][3];

    if (s == 0) {
        float th = ang[2 * r + 0];
        float ph = ang[2 * r + 1];
        float st, ct, sp, cp;
        sincosf(th, &st, &ct);
        sincosf(ph, &sp, &cp);
        float stcp = st * cp;
        float stsp = st * sp;
        Ysh[0] = Y00f;
        Ysh[1] = H3f * stsp;
        Ysh[2] = H3f * ct;
        Ysh[3] = H3f * stcp;
        Ysh[4] = H15f * stcp * stsp;
        Ysh[5] = H15f * stsp * ct;
        Ysh[6] = Q5f * (3.0f * ct * ct - 1.0f);
        Ysh[7] = H15f * stcp * ct;
        Ysh[8] = Q15f * (stcp * stcp - stsp * stsp);
    }
    __syncthreads();

    // Preload Y to registers (broadcast LDS, conflict-free)
    float Y[9];
#pragma unroll
    for (int i = 0; i < 9; i++) Y[i] = Ysh[i];

    const int sg = r * NSAMP + s;
    const float px = pos[3 * sg + 0];
    const float py = pos[3 * sg + 1];
    const float pz = pos[3 * sg + 2];
    const float d  = dist[sg];

    int ix = (int)floorf(px);
    int iy = (int)floorf(py);
    int iz = (int)floorf(pz);
    const float fx = px - (float)ix;
    const float fy = py - (float)iy;
    const float fz = pz - (float)iz;
    const int gmax = GDIM - 1;
    const int ix0 = min(max(ix, 0), gmax), ix1 = min(max(ix + 1, 0), gmax);
    const int iy0 = min(max(iy, 0), gmax), iy1 = min(max(iy + 1, 0), gmax);
    const int iz0 = min(max(iz, 0), gmax), iz1 = min(max(iz + 1, 0), gmax);

    const float wx0 = 1.0f - fx, wx1 = fx;
    const float wy0 = 1.0f - fy, wy1 = fy;
    const float wz0 = 1.0f - fz, wz1 = fz;

    const float w0 = wx0 * wy0 * wz0;
    const float w1 = wx0 * wy0 * wz1;
    const float w2 = wx0 * wy1 * wz0;
    const float w3 = wx0 * wy1 * wz1;
    const float w4 = wx1 * wy0 * wz0;
    const float w5 = wx1 * wy0 * wz1;
    const float w6 = wx1 * wy1 * wz0;
    const float w7 = wx1 * wy1 * wz1;

    // Corner bases in float4 units: ((ix*G+iy)*G+iz)*28 floats = *7 float4
    const float4* __restrict__ g4 = (const float4*)grid;
    const int b000 = ((ix0 * GDIM + iy0) * GDIM + iz0) * 7;
    const int b001 = ((ix0 * GDIM + iy0) * GDIM + iz1) * 7;
    const int b010 = ((ix0 * GDIM + iy1) * GDIM + iz0) * 7;
    const int b011 = ((ix0 * GDIM + iy1) * GDIM + iz1) * 7;
    const int b100 = ((ix1 * GDIM + iy0) * GDIM + iz0) * 7;
    const int b101 = ((ix1 * GDIM + iy0) * GDIM + iz1) * 7;
    const int b110 = ((ix1 * GDIM + iy1) * GDIM + iz0) * 7;
    const int b111 = ((ix1 * GDIM + iy1) * GDIM + iz1) * 7;

    float sigma = 0.0f;
    float rgbR = 0.0f, rgbG = 0.0f, rgbB = 0.0f;

#pragma unroll
    for (int c4 = 0; c4 < 7; c4++) {
        const float4 a0 = __ldg(&g4[b000 + c4]);
        const float4 a1 = __ldg(&g4[b001 + c4]);
        const float4 a2 = __ldg(&g4[b010 + c4]);
        const float4 a3 = __ldg(&g4[b011 + c4]);
        const float4 a4 = __ldg(&g4[b100 + c4]);
        const float4 a5 = __ldg(&g4[b101 + c4]);
        const float4 a6 = __ldg(&g4[b110 + c4]);
        const float4 a7 = __ldg(&g4[b111 + c4]);

        float f[4];
        f[0] = w0*a0.x + w1*a1.x + w2*a2.x + w3*a3.x + w4*a4.x + w5*a5.x + w6*a6.x + w7*a7.x;
        f[1] = w0*a0.y + w1*a1.y + w2*a2.y + w3*a3.y + w4*a4.y + w5*a5.y + w6*a6.y + w7*a7.y;
        f[2] = w0*a0.z + w1*a1.z + w2*a2.z + w3*a3.z + w4*a4.z + w5*a5.z + w6*a6.z + w7*a7.z;
        f[3] = w0*a0.w + w1*a1.w + w2*a2.w + w3*a3.w + w4*a4.w + w5*a5.w + w6*a6.w + w7*a7.w;

#pragma unroll
        for (int k = 0; k < 4; k++) {
            const int ch = 4 * c4 + k;   // compile-time constant after unroll
            if (ch == 0) {
                sigma = f[k];
            } else {
                const int q = (ch - 1) / 9;   // color channel
                const int n = (ch - 1) % 9;   // SH index
                const float t = f[k] * Y[n];
                if (q == 0)      rgbR += t;
                else if (q == 1) rgbG += t;
                else             rgbB += t;
            }
        }
    }

    // att + inclusive block scan of att over 128 samples
    const float att = expf(-sigma * d);
    float x = att;
#pragma unroll
    for (int o = 1; o < 32; o <<= 1) {
        float ysh = __shfl_up_sync(0xffffffffu, x, o);
        if (lane >= o) x += ysh;
    }
    if (lane == 31) warp_att[wid] = x;
    __syncthreads();

    float offset = 0.0f;
#pragma unroll
    for (int i = 0; i < 3; i++) {
        if (i < wid) offset += warp_att[i];
    }
    const float trans = x + offset;               // inclusive cumsum of att
    const float weight = trans * (1.0f - att);

    float vr = weight * rgbR;
    float vg = weight * rgbG;
    float vb = weight * rgbB;
#pragma unroll
    for (int o = 16; o > 0; o >>= 1) {
        vr += __shfl_down_sync(0xffffffffu, vr, o);
        vg += __shfl_down_sync(0xffffffffu, vg, o);
        vb += __shfl_down_sync(0xffffffffu, vb, o);
    }
    if (lane == 0) {
        warp_rgb[wid][0] = vr;
        warp_rgb[wid][1] = vg;
        warp_rgb[wid][2] = vb;
    }
    __syncthreads();

    if (s == 0) {
        float R = 0.0f, Gg = 0.0f, B = 0.0f;
#pragma unroll
        for (int i = 0; i < 4; i++) {
            R  += warp_rgb[i][0];
            Gg += warp_rgb[i][1];
            B  += warp_rgb[i][2];
        }
        out[3 * r + 0] = R;
        out[3 * r + 1] = Gg;
        out[3 * r + 2] = B;
    }
}

extern "C" void kernel_launch(void* const* d_in, const int* in_sizes, int n_in,
                              void* d_out, int out_size) {
    const float* grid = (const float*)d_in[0];
    const float* pos  = (const float*)d_in[1];
    const float* dst  = (const float*)d_in[2];
    const float* ang  = (const float*)d_in[3];
    float* out = (float*)d_out;
    plenoxel_kernel<<<NRAYS, NSAMP>>>(grid, pos, dst, ang, out);
}

// round 2
// speedup vs baseline: 1.3384x; 1.3384x over previous
#include <cuda_runtime.h>
#include <cuda_bf16.h>

#define GDIM 128
#define NRAYS 2048
#define NSAMP 128
#define VD 28
#define BTHREADS 256
#define BWARPS 8
#define SAMP_PER_WARP (NSAMP / BWARPS)

// SH constants
#define Y00f 0.28209479177387814f
#define H3f  0.4886025119029199f
#define H15f 1.0925484305920792f
#define Q5f  0.31539156525252005f
#define Q15f 0.5462742152960396f

__global__ __launch_bounds__(BTHREADS, 6) void plenoxel_kernel(
    const float* __restrict__ grid,   // (G,G,G,28)
    const float* __restrict__ pos,    // (R,S,3)
    const float* __restrict__ dist,   // (R,S)
    const float* __restrict__ ang,    // (R,2)
    float* __restrict__ out)          // (R,3)
{
    const int r    = blockIdx.x;
    const int tid  = threadIdx.x;
    const int lane = tid & 31;
    const int wid  = tid >> 5;

    __shared__ float spos[NSAMP * 3];
    __shared__ float sdist[NSAMP];
    __shared__ float Ysh[9];
    __shared__ float att_s[NSAMP];
    __shared__ float rgb_s[NSAMP][3];
    __shared__ float warp_att[4];
    __shared__ float warp_rgb[4][3];

    // Stage per-ray sample data coalesced
    for (int i = tid; i < NSAMP * 3; i += BTHREADS)
        spos[i] = pos[r * NSAMP * 3 + i];
    for (int i = tid; i < NSAMP; i += BTHREADS)
        sdist[i] = dist[r * NSAMP + i];
    if (tid == 0) {
        float th = ang[2 * r + 0];
        float ph = ang[2 * r + 1];
        float st, ct, sp, cp;
        sincosf(th, &st, &ct);
        sincosf(ph, &sp, &cp);
        float stcp = st * cp;
        float stsp = st * sp;
        Ysh[0] = Y00f;
        Ysh[1] = H3f * stsp;
        Ysh[2] = H3f * ct;
        Ysh[3] = H3f * stcp;
        Ysh[4] = H15f * stcp * stsp;
        Ysh[5] = H15f * stsp * ct;
        Ysh[6] = Q5f * (3.0f * ct * ct - 1.0f);
        Ysh[7] = H15f * stcp * ct;
        Ysh[8] = Q15f * (stcp * stcp - stsp * stsp);
    }
    __syncthreads();

    // Per-lane SH coefficient & color channel (lane = feature channel)
    float ycoef = 0.0f;
    int   q     = 3;                        // 3 = contributes to nothing
    if (lane >= 1 && lane < VD) {
        const int n = (lane - 1) % 9;
        q     = (lane - 1) / 9;
        ycoef = Ysh[n];
    }

    // ---- Phase 1: one sample per warp-iteration, lane-per-channel gather ----
    for (int i = 0; i < SAMP_PER_WARP; i++) {
        const int s = wid * SAMP_PER_WARP + i;
        const float px = spos[3 * s + 0];
        const float py = spos[3 * s + 1];
        const float pz = spos[3 * s + 2];
        const float d  = sdist[s];

        int ix = (int)floorf(px);
        int iy = (int)floorf(py);
        int iz = (int)floorf(pz);
        const float fx = px - (float)ix;
        const float fy = py - (float)iy;
        const float fz = pz - (float)iz;
        const int gmax = GDIM - 1;
        const int ix0 = min(max(ix, 0), gmax), ix1 = min(max(ix + 1, 0), gmax);
        const int iy0 = min(max(iy, 0), gmax), iy1 = min(max(iy + 1, 0), gmax);
        const int iz0 = min(max(iz, 0), gmax), iz1 = min(max(iz + 1, 0), gmax);

        const float wx0 = 1.0f - fx, wx1 = fx;
        const float wy0 = 1.0f - fy, wy1 = fy;
        const float wz0 = 1.0f - fz, wz1 = fz;

        const float w0 = wx0 * wy0 * wz0;
        const float w1 = wx0 * wy0 * wz1;
        const float w2 = wx0 * wy1 * wz0;
        const float w3 = wx0 * wy1 * wz1;
        const float w4 = wx1 * wy0 * wz0;
        const float w5 = wx1 * wy0 * wz1;
        const float w6 = wx1 * wy1 * wz0;
        const float w7 = wx1 * wy1 * wz1;

        const int b000 = ((ix0 * GDIM + iy0) * GDIM + iz0) * VD + lane;
        const int b001 = ((ix0 * GDIM + iy0) * GDIM + iz1) * VD + lane;
        const int b010 = ((ix0 * GDIM + iy1) * GDIM + iz0) * VD + lane;
        const int b011 = ((ix0 * GDIM + iy1) * GDIM + iz1) * VD + lane;
        const int b100 = ((ix1 * GDIM + iy0) * GDIM + iz0) * VD + lane;
        const int b101 = ((ix1 * GDIM + iy0) * GDIM + iz1) * VD + lane;
        const int b110 = ((ix1 * GDIM + iy1) * GDIM + iz0) * VD + lane;
        const int b111 = ((ix1 * GDIM + iy1) * GDIM + iz1) * VD + lane;

        float feats = 0.0f;
        if (lane < VD) {
            const float a0 = __ldg(grid + b000);
            const float a1 = __ldg(grid + b001);
            const float a2 = __ldg(grid + b010);
            const float a3 = __ldg(grid + b011);
            const float a4 = __ldg(grid + b100);
            const float a5 = __ldg(grid + b101);
            const float a6 = __ldg(grid + b110);
            const float a7 = __ldg(grid + b111);
            feats = w0*a0 + w1*a1 + w2*a2 + w3*a3
                  + w4*a4 + w5*a5 + w6*a6 + w7*a7;
        }

        const float sigma = __shfl_sync(0xffffffffu, feats, 0);
        const float att   = expf(-sigma * d);

        const float t = feats * ycoef;
        float vr = (q == 0) ? t : 0.0f;
        float vg = (q == 1) ? t : 0.0f;
        float vb = (q == 2) ? t : 0.0f;
#pragma unroll
        for (int o = 16; o > 0; o >>= 1) {
            vr += __shfl_xor_sync(0xffffffffu, vr, o);
            vg += __shfl_xor_sync(0xffffffffu, vg, o);
            vb += __shfl_xor_sync(0xffffffffu, vb, o);
        }
        if (lane == 0) {
            att_s[s]    = att;
            rgb_s[s][0] = vr;
            rgb_s[s][1] = vg;
            rgb_s[s][2] = vb;
        }
    }
    __syncthreads();

    // ---- Phase 2: 128-wide inclusive scan of att, weight, reduce rgb ----
    float x = 0.0f, att = 0.0f;
    if (tid < NSAMP) {
        att = att_s[tid];
        x   = att;
    }
#pragma unroll
    for (int o = 1; o < 32; o <<= 1) {
        float ysh = __shfl_up_sync(0xffffffffu, x, o);
        if (lane >= o) x += ysh;
    }
    if (tid < NSAMP && lane == 31) warp_att[wid] = x;
    __syncthreads();

    float vr = 0.0f, vg = 0.0f, vb = 0.0f;
    if (tid < NSAMP) {
        float offset = 0.0f;
#pragma unroll
        for (int i = 0; i < 3; i++)
            if (i < wid) offset += warp_att[i];
        const float trans  = x + offset;
        const float weight = trans * (1.0f - att);
        vr = weight * rgb_s[tid][0];
        vg = weight * rgb_s[tid][1];
        vb = weight * rgb_s[tid][2];
    }
#pragma unroll
    for (int o = 16; o > 0; o >>= 1) {
        vr += __shfl_down_sync(0xffffffffu, vr, o);
        vg += __shfl_down_sync(0xffffffffu, vg, o);
        vb += __shfl_down_sync(0xffffffffu, vb, o);
    }
    if (tid < NSAMP && lane == 0) {
        warp_rgb[wid][0] = vr;
        warp_rgb[wid][1] = vg;
        warp_rgb[wid][2] = vb;
    }
    __syncthreads();

    if (tid == 0) {
        float R = 0.0f, Gg = 0.0f, B = 0.0f;
#pragma unroll
        for (int i = 0; i < 4; i++) {
            R  += warp_rgb[i][0];
            Gg += warp_rgb[i][1];
            B  += warp_rgb[i][2];
        }
        out[3 * r + 0] = R;
        out[3 * r + 1] = Gg;
        out[3 * r + 2] = B;
    }
}

extern "C" void kernel_launch(void* const* d_in, const int* in_sizes, int n_in,
                              void* d_out, int out_size) {
    const float* grid = (const float*)d_in[0];
    const float* pos  = (const float*)d_in[1];
    const float* dst  = (const float*)d_in[2];
    const float* ang  = (const float*)d_in[3];
    float* out = (float*)d_out;
    plenoxel_kernel<<<NRAYS, BTHREADS>>>(grid, pos, dst, ang, out);
}